// round 15
// baseline (speedup 1.0000x reference)
#include <cuda_runtime.h>
#include <stdint.h>

// Problem dims
#define BSZ   4096
#define INF   1024
#define OUTF  2048
#define BF    8388608u     // BSZ*OUTF (per-timestep element count)

// libdevice precise functions (immune to fast-math substitution)
extern "C" __device__ float __nv_logf(float);
extern "C" __device__ float __nv_rsqrtf(float);

// Scratch + rowblock-completion counters (device globals: no allocation)
__device__ float g_raw[BSZ * OUTF];
__device__ int   g_cnt[32];

__global__ void init_kernel(void)
{
    if (threadIdx.x < 32) g_cnt[threadIdx.x] = 0;
}

// ---------------------------------------------------------------------------
// GEMM tile (verbatim R6 arithmetic): raw[m,n] = sum_k x[m,k]*W[n,k] + b[n]
// 128x128 tile, BK=16, 256 threads, 8x8 microtile, k strictly ascending.
// ---------------------------------------------------------------------------
__device__ __forceinline__ void gemm_tile(
    const float* __restrict__ X, const float* __restrict__ W,
    const float* __restrict__ bias, float* __restrict__ out,
    int m0, int n0)
{
    __shared__ float As[16][128];
    __shared__ float Bs[16][128];

    const int tid = threadIdx.x;
    const int tn = (tid & 15) * 8;
    const int tm = (tid >> 4) * 8;

    const int qrow = tid >> 2;        // 0..63
    const int qcol = (tid & 3) * 4;   // 0,4,8,12
    const float* xptr = X + (size_t)(m0 + qrow) * INF + qcol;
    const float* wptr = W + (size_t)(n0 + qrow) * INF + qcol;

    float c[8][8];
#pragma unroll
    for (int i = 0; i < 8; i++)
#pragma unroll
        for (int j = 0; j < 8; j++) c[i][j] = 0.0f;

    float4 ar[2], br[2];
    ar[0] = *(const float4*)(xptr);
    ar[1] = *(const float4*)(xptr + (size_t)64 * INF);
    br[0] = *(const float4*)(wptr);
    br[1] = *(const float4*)(wptr + (size_t)64 * INF);

    for (int kt = 0; kt < INF / 16; kt++) {
#pragma unroll
        for (int s = 0; s < 2; s++) {
            const int row = qrow + s * 64;
            As[qcol + 0][row] = ar[s].x; As[qcol + 1][row] = ar[s].y;
            As[qcol + 2][row] = ar[s].z; As[qcol + 3][row] = ar[s].w;
            Bs[qcol + 0][row] = br[s].x; Bs[qcol + 1][row] = br[s].y;
            Bs[qcol + 2][row] = br[s].z; Bs[qcol + 3][row] = br[s].w;
        }
        __syncthreads();

        if (kt < INF / 16 - 1) {
            const float* xp = xptr + (kt + 1) * 16;
            const float* wp = wptr + (kt + 1) * 16;
            ar[0] = *(const float4*)(xp);
            ar[1] = *(const float4*)(xp + (size_t)64 * INF);
            br[0] = *(const float4*)(wp);
            br[1] = *(const float4*)(wp + (size_t)64 * INF);
        }

#pragma unroll
        for (int k = 0; k < 16; k++) {
            float4 a0 = *(const float4*)(&As[k][tm]);
            float4 a1 = *(const float4*)(&As[k][tm + 4]);
            float4 b0 = *(const float4*)(&Bs[k][tn]);
            float4 b1 = *(const float4*)(&Bs[k][tn + 4]);
            float av[8] = {a0.x, a0.y, a0.z, a0.w, a1.x, a1.y, a1.z, a1.w};
            float bv[8] = {b0.x, b0.y, b0.z, b0.w, b1.x, b1.y, b1.z, b1.w};
#pragma unroll
            for (int i = 0; i < 8; i++)
#pragma unroll
                for (int j = 0; j < 8; j++)
                    c[i][j] = fmaf(av[i], bv[j], c[i][j]);
        }
        __syncthreads();
    }

#pragma unroll
    for (int i = 0; i < 8; i++) {
        float* orow = out + (size_t)(m0 + tm + i) * OUTF + n0 + tn;
#pragma unroll
        for (int j = 0; j < 8; j++)
            orow[j] = __fadd_rn(c[i][j], bias[n0 + tn + j]);
    }

    // publish: this rowblock's tile is done
    __threadfence();
    __syncthreads();
    if (tid == 0) atomicAdd(&g_cnt[m0 >> 7], 1);
}

// ---------------------------------------------------------------------------
// JAX threefry2x32, key = (0, 42)
// ---------------------------------------------------------------------------
__device__ __forceinline__ void tf2x32(uint32_t x0, uint32_t x1,
                                       uint32_t& r0, uint32_t& r1)
{
    const uint32_t ks0 = 0u;
    const uint32_t ks1 = 42u;
    const uint32_t ks2 = 0x1BD11BDAu ^ 42u;
#define TFR(r) { x0 += x1; x1 = __funnelshift_l(x1, x1, (r)); x1 ^= x0; }
    x0 += ks0; x1 += ks1;
    TFR(13) TFR(15) TFR(26) TFR(6)
    x0 += ks1; x1 += ks2 + 1u;
    TFR(17) TFR(29) TFR(16) TFR(24)
    x0 += ks2; x1 += ks0 + 2u;
    TFR(13) TFR(15) TFR(26) TFR(6)
    x0 += ks0; x1 += ks1 + 3u;
    TFR(17) TFR(29) TFR(16) TFR(24)
    x0 += ks1; x1 += ks2 + 4u;
    TFR(13) TFR(15) TFR(26) TFR(6)
    x0 += ks2; x1 += ks0 + 5u;
#undef TFR
    r0 = x0; r1 = x1;
}

// bits -> 0.3 * (sqrt(2) * erfinv(u)) — XLA-exact (unfused, EmitLog1p, Giles)
__device__ __forceinline__ float bits_to_noise(uint32_t bits)
{
    float f = __fsub_rn(__uint_as_float((bits >> 9) | 0x3f800000u), 1.0f);
    float u = __fadd_rn(__fmul_rn(f, 2.0f), -0.99999994f);
    u = fmaxf(u, -0.99999994f);

    float y = -__fmul_rn(u, u);
    float w;
    if (fabsf(y) < 1e-4f) {
        w = __fmul_rn(__fadd_rn(__fmul_rn(-0.5f, y), 1.0f), y);
    } else {
        w = __nv_logf(__fadd_rn(y, 1.0f));
    }
    w = -w;

    float p;
    if (w < 5.0f) {
        w = __fsub_rn(w, 2.5f);
        p = 2.81022636e-08f;
        p = __fadd_rn(__fmul_rn(p, w),  3.43273939e-07f);
        p = __fadd_rn(__fmul_rn(p, w), -3.5233877e-06f);
        p = __fadd_rn(__fmul_rn(p, w), -4.39150654e-06f);
        p = __fadd_rn(__fmul_rn(p, w),  0.00021858087f);
        p = __fadd_rn(__fmul_rn(p, w), -0.00125372503f);
        p = __fadd_rn(__fmul_rn(p, w), -0.00417768164f);
        p = __fadd_rn(__fmul_rn(p, w),  0.246640727f);
        p = __fadd_rn(__fmul_rn(p, w),  1.50140941f);
    } else {
        w = __fsub_rn(__fsqrt_rn(w), 3.0f);
        p = -0.000200214257f;
        p = __fadd_rn(__fmul_rn(p, w),  0.000100950558f);
        p = __fadd_rn(__fmul_rn(p, w),  0.00134934322f);
        p = __fadd_rn(__fmul_rn(p, w), -0.00367342844f);
        p = __fadd_rn(__fmul_rn(p, w),  0.00573950773f);
        p = __fadd_rn(__fmul_rn(p, w), -0.0076224613f);
        p = __fadd_rn(__fmul_rn(p, w),  0.00943887047f);
        p = __fadd_rn(__fmul_rn(p, w),  1.00167406f);
        p = __fadd_rn(__fmul_rn(p, w),  2.83297682f);
    }
    float r = __fmul_rn(p, u);
    r = __fmul_rn(1.41421356f, r);
    return __fmul_rn(0.3f, r);
}

// XLA f32 rational tanh (unfused)
__device__ __forceinline__ float xla_tanhf(float x)
{
    float ax = fabsf(x);
    float xc = fminf(fmaxf(x, -7.90531110763549805f), 7.90531110763549805f);
    float x2 = __fmul_rn(xc, xc);
    float np_ = -2.76076847742355e-16f;
    np_ = __fadd_rn(__fmul_rn(np_, x2),  2.00018790482477e-13f);
    np_ = __fadd_rn(__fmul_rn(np_, x2), -8.60467152213735e-11f);
    np_ = __fadd_rn(__fmul_rn(np_, x2),  5.12229709037114e-08f);
    np_ = __fadd_rn(__fmul_rn(np_, x2),  1.48572235717979e-05f);
    np_ = __fadd_rn(__fmul_rn(np_, x2),  6.37261928875436e-04f);
    np_ = __fadd_rn(__fmul_rn(np_, x2),  4.89352455891786e-03f);
    np_ = __fmul_rn(np_, xc);
    float dp = 1.19825839466702e-06f;
    dp = __fadd_rn(__fmul_rn(dp, x2),  1.18534705686654e-04f);
    dp = __fadd_rn(__fmul_rn(dp, x2),  2.26843463243900e-03f);
    dp = __fadd_rn(__fmul_rn(dp, x2),  4.89352518554385e-03f);
    float r = __fdiv_rn(np_, dp);
    return (ax < 0.0004f) ? x : r;
}

__device__ __forceinline__ float block_reduce(float v, float* sbuf, int tid)
{
#pragma unroll
    for (int o = 16; o > 0; o >>= 1) v += __shfl_xor_sync(0xffffffffu, v, o);
    if ((tid & 31) == 0) sbuf[tid >> 5] = v;
    __syncthreads();
    if (tid < 8) {
        float t = sbuf[tid];
#pragma unroll
        for (int o = 4; o > 0; o >>= 1) t += __shfl_xor_sync(0xffu, t, o);
        if (tid == 0) sbuf[0] = t;
    }
    __syncthreads();
    float r = sbuf[0];
    __syncthreads();
    return r;
}

// ---------------------------------------------------------------------------
// SNN row (verbatim R6 arithmetic): LN + tanh + threefry noise + 8 Izhikevich
// steps for one global batch row b. Gated on the row's gemm rowblock.
// ---------------------------------------------------------------------------
__device__ __forceinline__ void snn_row(
    const float* __restrict__ raw_g,
    const float* __restrict__ gamma, const float* __restrict__ beta,
    const float* __restrict__ cmag, float* __restrict__ out, int b)
{
    __shared__ float sbuf[8];
    const int tid = threadIdx.x;

    // wait until all 16 tiles of this rowblock are published
    if (tid == 0) {
        const int rb = b >> 7;
        while (atomicAdd(&g_cnt[rb], 0) < 16) __nanosleep(128);
        __threadfence();
    }
    __syncthreads();

    const float* rowp = raw_g + (size_t)b * OUTF;

    float vals[8];
    float s = 0.0f;
#pragma unroll
    for (int j = 0; j < 8; j++) {
        vals[j] = rowp[tid + 256 * j];
        s += vals[j];
    }
    s = block_reduce(s, sbuf, tid);
    const float mu = __fmul_rn(s, (1.0f / 2048.0f));

    float s2 = 0.0f;
#pragma unroll
    for (int j = 0; j < 8; j++) {
        float d = __fsub_rn(vals[j], mu);
        s2 += __fmul_rn(d, d);
    }
    s2 = block_reduce(s2, sbuf, tid);
    const float var = __fmul_rn(s2, (1.0f / 2048.0f));
    const float rstd = __nv_rsqrtf(__fadd_rn(var, 1e-5f));
    const float imag = fabsf(cmag[0]);

#pragma unroll 1
    for (int j = 0; j < 8; j++) {
        const int f = tid + 256 * j;
        const float d  = __fsub_rn(vals[j], mu);
        const float ln = __fadd_rn(__fmul_rn(__fmul_rn(d, rstd), gamma[f]), beta[f]);
        const float I  = __fmul_rn(xla_tanhf(ln), imag);

        const uint32_t e = (uint32_t)b * (uint32_t)OUTF + (uint32_t)f;
        float nz[8];
#pragma unroll
        for (int t = 0; t < 8; t++) {
            uint32_t r0, r1;
            tf2x32(0u, (uint32_t)t * BF + e, r0, r1);
            nz[t] = bits_to_noise(r0 ^ r1);
        }

        float v = -65.0f, uu = -13.0f, acc = 0.0f;
#pragma unroll
        for (int t = 0; t < 8; t++) {
            const float It = __fadd_rn(I, nz[t]);
            float t1 = __fmul_rn(__fmul_rn(0.04f, v), v);
            float t2 = __fmul_rn(5.0f, v);
            float sdv = __fadd_rn(t1, t2);
            sdv = __fadd_rn(sdv, 140.0f);
            sdv = __fsub_rn(sdv, uu);
            sdv = __fadd_rn(sdv, It);
            const float vn = fminf(fmaxf(__fadd_rn(v, sdv), -100.0f), 60.0f);
            float tu = __fsub_rn(__fmul_rn(0.2f, v), uu);
            tu = __fmul_rn(0.02f, tu);
            const float un = fminf(fmaxf(__fadd_rn(uu, tu), -100.0f), 100.0f);
            const bool spk = (vn >= 30.0f);
            v  = spk ? -65.0f : vn;
            uu = spk ? __fadd_rn(un, 8.0f) : un;
            acc += spk ? 1.0f : 0.0f;
        }
        out[(size_t)b * OUTF + f] = __fmul_rn(acc, 0.125f);
    }
}

// ---------------------------------------------------------------------------
// Fused kernel: role by blockIdx. Bid layout (scheduler runs low bids first):
//   [0, 32):       gemm tiles of rowblocks 0,1  (16 tiles each)
//   [32, 4352):    30 groups g=0..29, each 144 bids:
//                    [0,16)   gemm tiles of rowblock g+2
//                    [16,144) snn rows of rowblock g   (ready 2 groups later)
//   [4352, 4608):  snn rows of rowblocks 30,31
// Every snn CTA depends only on lower-bid gemm CTAs -> deadlock-free; the
// interleave keeps gemm (fma-pipe) and snn (alu-pipe) CTAs co-resident.
// ---------------------------------------------------------------------------
__global__ __launch_bounds__(256, 2)
void fused_kernel(const float* __restrict__ X, const float* __restrict__ W,
                  const float* __restrict__ bias,
                  const float* __restrict__ gamma, const float* __restrict__ beta,
                  const float* __restrict__ cmag,
                  float* __restrict__ raw, float* __restrict__ out)
{
    const int bid = blockIdx.x;
    if (bid < 32) {
        gemm_tile(X, W, bias, raw, (bid >> 4) * 128, (bid & 15) * 128);
    } else if (bid < 4352) {
        const int q = bid - 32;
        const int g = q / 144;
        const int r = q - g * 144;
        if (r < 16) {
            gemm_tile(X, W, bias, raw, (g + 2) * 128, r * 128);
        } else {
            snn_row(raw, gamma, beta, cmag, out, g * 128 + (r - 16));
        }
    } else {
        snn_row(raw, gamma, beta, cmag, out, 3840 + (bid - 4352));
    }
}

// ---------------------------------------------------------------------------
extern "C" void kernel_launch(void* const* d_in, const int* in_sizes, int n_in,
                              void* d_out, int out_size)
{
    const float* x     = (const float*)d_in[0];  // [4096,1024]
    const float* W     = (const float*)d_in[1];  // [2048,1024]
    const float* b_lin = (const float*)d_in[2];  // [2048]
    const float* gamma = (const float*)d_in[3];  // [2048]
    const float* beta  = (const float*)d_in[4];  // [2048]
    const float* cmag  = (const float*)d_in[5];  // [1]
    float* out = (float*)d_out;                  // [4096,2048]

    float* raw;
    cudaGetSymbolAddress((void**)&raw, g_raw);

    init_kernel<<<1, 32>>>();
    fused_kernel<<<4608, 256>>>(x, W, b_lin, gamma, beta, cmag, raw, out);
}

// round 16
// speedup vs baseline: 2.0568x; 2.0568x over previous
#include <cuda_runtime.h>
#include <stdint.h>

// Problem dims
#define BSZ   4096
#define INF   1024
#define OUTF  2048
#define BF    8388608u     // BSZ*OUTF (per-timestep element count)

// libdevice precise functions (immune to fast-math substitution)
extern "C" __device__ float __nv_logf(float);
extern "C" __device__ float __nv_rsqrtf(float);

// Scratch for raw = x@W.T + b  (device global: no allocation allowed)
__device__ float g_raw[BSZ * OUTF];

// ---------------------------------------------------------------------------
// Kernel 1: fp32 SGEMM  raw[m,n] = sum_k x[m,k]*W[n,k] + b[n]
// 128x128 tile, BK=16, 256 threads, 8x8 microtile, single accumulator,
// k strictly ascending. (Proven R6: rel_err 6.176567e-4, ~460us.)
// ---------------------------------------------------------------------------
__global__ __launch_bounds__(256, 2)
void gemm_kernel(const float* __restrict__ X, const float* __restrict__ W,
                 const float* __restrict__ bias, float* __restrict__ out)
{
    __shared__ float As[16][128];
    __shared__ float Bs[16][128];

    const int n0 = blockIdx.x * 128;
    const int m0 = blockIdx.y * 128;
    const int tid = threadIdx.x;
    const int tn = (tid & 15) * 8;
    const int tm = (tid >> 4) * 8;

    const int qrow = tid >> 2;        // 0..63
    const int qcol = (tid & 3) * 4;   // 0,4,8,12
    const float* xptr = X + (size_t)(m0 + qrow) * INF + qcol;
    const float* wptr = W + (size_t)(n0 + qrow) * INF + qcol;

    float c[8][8];
#pragma unroll
    for (int i = 0; i < 8; i++)
#pragma unroll
        for (int j = 0; j < 8; j++) c[i][j] = 0.0f;

    float4 ar[2], br[2];
    ar[0] = *(const float4*)(xptr);
    ar[1] = *(const float4*)(xptr + (size_t)64 * INF);
    br[0] = *(const float4*)(wptr);
    br[1] = *(const float4*)(wptr + (size_t)64 * INF);

    for (int kt = 0; kt < INF / 16; kt++) {
#pragma unroll
        for (int s = 0; s < 2; s++) {
            const int row = qrow + s * 64;
            As[qcol + 0][row] = ar[s].x; As[qcol + 1][row] = ar[s].y;
            As[qcol + 2][row] = ar[s].z; As[qcol + 3][row] = ar[s].w;
            Bs[qcol + 0][row] = br[s].x; Bs[qcol + 1][row] = br[s].y;
            Bs[qcol + 2][row] = br[s].z; Bs[qcol + 3][row] = br[s].w;
        }
        __syncthreads();

        if (kt < INF / 16 - 1) {
            const float* xp = xptr + (kt + 1) * 16;
            const float* wp = wptr + (kt + 1) * 16;
            ar[0] = *(const float4*)(xp);
            ar[1] = *(const float4*)(xp + (size_t)64 * INF);
            br[0] = *(const float4*)(wp);
            br[1] = *(const float4*)(wp + (size_t)64 * INF);
        }

#pragma unroll
        for (int k = 0; k < 16; k++) {
            float4 a0 = *(const float4*)(&As[k][tm]);
            float4 a1 = *(const float4*)(&As[k][tm + 4]);
            float4 b0 = *(const float4*)(&Bs[k][tn]);
            float4 b1 = *(const float4*)(&Bs[k][tn + 4]);
            float av[8] = {a0.x, a0.y, a0.z, a0.w, a1.x, a1.y, a1.z, a1.w};
            float bv[8] = {b0.x, b0.y, b0.z, b0.w, b1.x, b1.y, b1.z, b1.w};
#pragma unroll
            for (int i = 0; i < 8; i++)
#pragma unroll
                for (int j = 0; j < 8; j++)
                    c[i][j] = fmaf(av[i], bv[j], c[i][j]);
        }
        __syncthreads();
    }

#pragma unroll
    for (int i = 0; i < 8; i++) {
        float* orow = out + (size_t)(m0 + tm + i) * OUTF + n0 + tn;
#pragma unroll
        for (int j = 0; j < 8; j++)
            orow[j] = __fadd_rn(c[i][j], bias[n0 + tn + j]);
    }
}

// ---------------------------------------------------------------------------
// JAX threefry2x32, key = (0, 42), counter = (0, c).
// Integer adds forced onto the FMA pipe via mad.lo.s32 with an opaque
// multiplier `one` (runtime 1; mod-2^32 exact, bit-identical results).
// The two ks0(=0) adds are dropped (exact no-ops).
// ---------------------------------------------------------------------------
#define KS1  42u
#define KS2  (0x1BD11BDAu ^ 42u)

// x += y * one  (IMAD, fma pipe)
#define ADDF(x, y) \
    asm("mad.lo.s32 %0, %1, %2, %0;" : "+r"(x) : "r"(y), "r"(one))
// x += imm * one (IMAD with immediate, fma pipe)
#define KADD(x, imm) \
    asm("mad.lo.s32 %0, %1, %2, %0;" : "+r"(x) : "r"(one), "n"(imm))

__device__ __forceinline__ void tf2x32(uint32_t x1, uint32_t one,
                                       uint32_t& r0, uint32_t& r1)
{
    uint32_t x0 = 0u;
    // initial injection: x0 += ks0(0) dropped; x1 += ks1
    KADD(x1, 42);
#define TFR(r) { ADDF(x0, x1); x1 = __funnelshift_l(x1, x1, (r)); x1 ^= x0; }
    TFR(13) TFR(15) TFR(26) TFR(6)
    KADD(x0, 42);              // ks1
    KADD(x1, (int)(KS2 + 1u));
    TFR(17) TFR(29) TFR(16) TFR(24)
    KADD(x0, (int)KS2);
    KADD(x1, 2);               // ks0 + 2
    TFR(13) TFR(15) TFR(26) TFR(6)
    /* x0 += ks0(0) dropped */
    KADD(x1, 45);              // ks1 + 3
    TFR(17) TFR(29) TFR(16) TFR(24)
    KADD(x0, 42);              // ks1
    KADD(x1, (int)(KS2 + 4u));
    TFR(13) TFR(15) TFR(26) TFR(6)
    KADD(x0, (int)KS2);
    KADD(x1, 5);               // ks0 + 5
#undef TFR
    r0 = x0; r1 = x1;
}

// bits -> 0.3 * (sqrt(2) * erfinv(u)) — XLA-exact (unfused, EmitLog1p, Giles)
__device__ __forceinline__ float bits_to_noise(uint32_t bits)
{
    float f = __fsub_rn(__uint_as_float((bits >> 9) | 0x3f800000u), 1.0f);
    float u = __fadd_rn(__fmul_rn(f, 2.0f), -0.99999994f);
    u = fmaxf(u, -0.99999994f);

    float y = -__fmul_rn(u, u);
    float w;
    if (fabsf(y) < 1e-4f) {
        w = __fmul_rn(__fadd_rn(__fmul_rn(-0.5f, y), 1.0f), y);
    } else {
        w = __nv_logf(__fadd_rn(y, 1.0f));
    }
    w = -w;

    float p;
    if (w < 5.0f) {
        w = __fsub_rn(w, 2.5f);
        p = 2.81022636e-08f;
        p = __fadd_rn(__fmul_rn(p, w),  3.43273939e-07f);
        p = __fadd_rn(__fmul_rn(p, w), -3.5233877e-06f);
        p = __fadd_rn(__fmul_rn(p, w), -4.39150654e-06f);
        p = __fadd_rn(__fmul_rn(p, w),  0.00021858087f);
        p = __fadd_rn(__fmul_rn(p, w), -0.00125372503f);
        p = __fadd_rn(__fmul_rn(p, w), -0.00417768164f);
        p = __fadd_rn(__fmul_rn(p, w),  0.246640727f);
        p = __fadd_rn(__fmul_rn(p, w),  1.50140941f);
    } else {
        w = __fsub_rn(__fsqrt_rn(w), 3.0f);
        p = -0.000200214257f;
        p = __fadd_rn(__fmul_rn(p, w),  0.000100950558f);
        p = __fadd_rn(__fmul_rn(p, w),  0.00134934322f);
        p = __fadd_rn(__fmul_rn(p, w), -0.00367342844f);
        p = __fadd_rn(__fmul_rn(p, w),  0.00573950773f);
        p = __fadd_rn(__fmul_rn(p, w), -0.0076224613f);
        p = __fadd_rn(__fmul_rn(p, w),  0.00943887047f);
        p = __fadd_rn(__fmul_rn(p, w),  1.00167406f);
        p = __fadd_rn(__fmul_rn(p, w),  2.83297682f);
    }
    float r = __fmul_rn(p, u);
    r = __fmul_rn(1.41421356f, r);
    return __fmul_rn(0.3f, r);
}

// XLA f32 rational tanh (unfused)
__device__ __forceinline__ float xla_tanhf(float x)
{
    float ax = fabsf(x);
    float xc = fminf(fmaxf(x, -7.90531110763549805f), 7.90531110763549805f);
    float x2 = __fmul_rn(xc, xc);
    float np_ = -2.76076847742355e-16f;
    np_ = __fadd_rn(__fmul_rn(np_, x2),  2.00018790482477e-13f);
    np_ = __fadd_rn(__fmul_rn(np_, x2), -8.60467152213735e-11f);
    np_ = __fadd_rn(__fmul_rn(np_, x2),  5.12229709037114e-08f);
    np_ = __fadd_rn(__fmul_rn(np_, x2),  1.48572235717979e-05f);
    np_ = __fadd_rn(__fmul_rn(np_, x2),  6.37261928875436e-04f);
    np_ = __fadd_rn(__fmul_rn(np_, x2),  4.89352455891786e-03f);
    np_ = __fmul_rn(np_, xc);
    float dp = 1.19825839466702e-06f;
    dp = __fadd_rn(__fmul_rn(dp, x2),  1.18534705686654e-04f);
    dp = __fadd_rn(__fmul_rn(dp, x2),  2.26843463243900e-03f);
    dp = __fadd_rn(__fmul_rn(dp, x2),  4.89352518554385e-03f);
    float r = __fdiv_rn(np_, dp);
    return (ax < 0.0004f) ? x : r;
}

__device__ __forceinline__ float block_reduce(float v, float* sbuf, int tid)
{
#pragma unroll
    for (int o = 16; o > 0; o >>= 1) v += __shfl_xor_sync(0xffffffffu, v, o);
    if ((tid & 31) == 0) sbuf[tid >> 5] = v;
    __syncthreads();
    if (tid < 8) {
        float t = sbuf[tid];
#pragma unroll
        for (int o = 4; o > 0; o >>= 1) t += __shfl_xor_sync(0xffu, t, o);
        if (tid == 0) sbuf[0] = t;
    }
    __syncthreads();
    float r = sbuf[0];
    __syncthreads();
    return r;
}

// ---------------------------------------------------------------------------
// Kernel 2: LN + tanh scaling + partitionable-threefry noise + 8-step
// Izhikevich, fused. One CTA per batch row; 256 threads x 8 features.
// Noise element (t,b,f): counter = (0, t*BF + b*OUTF + f), bits = r0 ^ r1.
// ---------------------------------------------------------------------------
__global__ __launch_bounds__(256)
void snn_kernel(const float* __restrict__ raw_g,
                const float* __restrict__ gamma, const float* __restrict__ beta,
                const float* __restrict__ cmag, float* __restrict__ out,
                uint32_t one)
{
    __shared__ float sbuf[8];
    const int b = blockIdx.x;
    const int tid = threadIdx.x;
    const float* rowp = raw_g + (size_t)b * OUTF;

    float vals[8];
    float s = 0.0f;
#pragma unroll
    for (int j = 0; j < 8; j++) {
        vals[j] = rowp[tid + 256 * j];
        s += vals[j];
    }
    s = block_reduce(s, sbuf, tid);
    const float mu = __fmul_rn(s, (1.0f / 2048.0f));

    float s2 = 0.0f;
#pragma unroll
    for (int j = 0; j < 8; j++) {
        float d = __fsub_rn(vals[j], mu);
        s2 += __fmul_rn(d, d);
    }
    s2 = block_reduce(s2, sbuf, tid);
    const float var = __fmul_rn(s2, (1.0f / 2048.0f));
    const float rstd = __nv_rsqrtf(__fadd_rn(var, 1e-5f));
    const float imag = fabsf(cmag[0]);

#pragma unroll 1
    for (int j = 0; j < 8; j++) {
        const int f = tid + 256 * j;
        const float d  = __fsub_rn(vals[j], mu);
        const float ln = __fadd_rn(__fmul_rn(__fmul_rn(d, rstd), gamma[f]), beta[f]);
        const float I  = __fmul_rn(xla_tanhf(ln), imag);

        const uint32_t e = (uint32_t)b * (uint32_t)OUTF + (uint32_t)f;
        float nz[8];
#pragma unroll
        for (int t = 0; t < 8; t++) {
            uint32_t r0, r1;
            tf2x32((uint32_t)t * BF + e, one, r0, r1);
            nz[t] = bits_to_noise(r0 ^ r1);
        }

        float v = -65.0f, uu = -13.0f, acc = 0.0f;
#pragma unroll
        for (int t = 0; t < 8; t++) {
            const float It = __fadd_rn(I, nz[t]);
            float t1 = __fmul_rn(__fmul_rn(0.04f, v), v);
            float t2 = __fmul_rn(5.0f, v);
            float sdv = __fadd_rn(t1, t2);
            sdv = __fadd_rn(sdv, 140.0f);
            sdv = __fsub_rn(sdv, uu);
            sdv = __fadd_rn(sdv, It);
            const float vn = fminf(fmaxf(__fadd_rn(v, sdv), -100.0f), 60.0f);
            float tu = __fsub_rn(__fmul_rn(0.2f, v), uu);
            tu = __fmul_rn(0.02f, tu);
            const float un = fminf(fmaxf(__fadd_rn(uu, tu), -100.0f), 100.0f);
            const bool spk = (vn >= 30.0f);
            v  = spk ? -65.0f : vn;
            uu = spk ? __fadd_rn(un, 8.0f) : un;
            acc += spk ? 1.0f : 0.0f;
        }
        out[(size_t)b * OUTF + f] = __fmul_rn(acc, 0.125f);
    }
}

// ---------------------------------------------------------------------------
extern "C" void kernel_launch(void* const* d_in, const int* in_sizes, int n_in,
                              void* d_out, int out_size)
{
    const float* x     = (const float*)d_in[0];  // [4096,1024]
    const float* W     = (const float*)d_in[1];  // [2048,1024]
    const float* b_lin = (const float*)d_in[2];  // [2048]
    const float* gamma = (const float*)d_in[3];  // [2048]
    const float* beta  = (const float*)d_in[4];  // [2048]
    const float* cmag  = (const float*)d_in[5];  // [1]
    float* out = (float*)d_out;                  // [4096,2048]

    float* raw;
    cudaGetSymbolAddress((void**)&raw, g_raw);

    // opaque 1: element count of current_mag — ptxas cannot fold this,
    // guaranteeing the mad.lo.s32 adds stay IMAD (fma pipe).
    const uint32_t one = (uint32_t)in_sizes[5];

    dim3 ggrid(OUTF / 128, BSZ / 128);
    gemm_kernel<<<ggrid, 256>>>(x, W, b_lin, raw);
    snn_kernel<<<BSZ, 256>>>(raw, gamma, beta, cmag, out, one);
}

// round 17
// speedup vs baseline: 2.0674x; 1.0051x over previous
#include <cuda_runtime.h>
#include <stdint.h>

// Problem dims
#define BSZ   4096
#define INF   1024
#define OUTF  2048
#define BF    8388608u     // BSZ*OUTF (per-timestep element count)

// libdevice precise functions (immune to fast-math substitution)
extern "C" __device__ float __nv_logf(float);
extern "C" __device__ float __nv_rsqrtf(float);

// Scratch for raw = x@W.T + b  (device global: no allocation allowed)
__device__ float g_raw[BSZ * OUTF];

// ---------------------------------------------------------------------------
// Kernel 1: fp32 SGEMM  raw[m,n] = sum_k x[m,k]*W[n,k] + b[n]
// 128x128 tile, BK=16, 256 threads, 8x8 microtile, single accumulator,
// k strictly ascending. (Proven: rel_err 6.176567e-4; at FFMA roofline.)
// ---------------------------------------------------------------------------
__global__ __launch_bounds__(256, 2)
void gemm_kernel(const float* __restrict__ X, const float* __restrict__ W,
                 const float* __restrict__ bias, float* __restrict__ out)
{
    __shared__ float As[16][128];
    __shared__ float Bs[16][128];

    const int n0 = blockIdx.x * 128;
    const int m0 = blockIdx.y * 128;
    const int tid = threadIdx.x;
    const int tn = (tid & 15) * 8;
    const int tm = (tid >> 4) * 8;

    const int qrow = tid >> 2;        // 0..63
    const int qcol = (tid & 3) * 4;   // 0,4,8,12
    const float* xptr = X + (size_t)(m0 + qrow) * INF + qcol;
    const float* wptr = W + (size_t)(n0 + qrow) * INF + qcol;

    float c[8][8];
#pragma unroll
    for (int i = 0; i < 8; i++)
#pragma unroll
        for (int j = 0; j < 8; j++) c[i][j] = 0.0f;

    float4 ar[2], br[2];
    ar[0] = *(const float4*)(xptr);
    ar[1] = *(const float4*)(xptr + (size_t)64 * INF);
    br[0] = *(const float4*)(wptr);
    br[1] = *(const float4*)(wptr + (size_t)64 * INF);

    for (int kt = 0; kt < INF / 16; kt++) {
#pragma unroll
        for (int s = 0; s < 2; s++) {
            const int row = qrow + s * 64;
            As[qcol + 0][row] = ar[s].x; As[qcol + 1][row] = ar[s].y;
            As[qcol + 2][row] = ar[s].z; As[qcol + 3][row] = ar[s].w;
            Bs[qcol + 0][row] = br[s].x; Bs[qcol + 1][row] = br[s].y;
            Bs[qcol + 2][row] = br[s].z; Bs[qcol + 3][row] = br[s].w;
        }
        __syncthreads();

        if (kt < INF / 16 - 1) {
            const float* xp = xptr + (kt + 1) * 16;
            const float* wp = wptr + (kt + 1) * 16;
            ar[0] = *(const float4*)(xp);
            ar[1] = *(const float4*)(xp + (size_t)64 * INF);
            br[0] = *(const float4*)(wp);
            br[1] = *(const float4*)(wp + (size_t)64 * INF);
        }

#pragma unroll
        for (int k = 0; k < 16; k++) {
            float4 a0 = *(const float4*)(&As[k][tm]);
            float4 a1 = *(const float4*)(&As[k][tm + 4]);
            float4 b0 = *(const float4*)(&Bs[k][tn]);
            float4 b1 = *(const float4*)(&Bs[k][tn + 4]);
            float av[8] = {a0.x, a0.y, a0.z, a0.w, a1.x, a1.y, a1.z, a1.w};
            float bv[8] = {b0.x, b0.y, b0.z, b0.w, b1.x, b1.y, b1.z, b1.w};
#pragma unroll
            for (int i = 0; i < 8; i++)
#pragma unroll
                for (int j = 0; j < 8; j++)
                    c[i][j] = fmaf(av[i], bv[j], c[i][j]);
        }
        __syncthreads();
    }

#pragma unroll
    for (int i = 0; i < 8; i++) {
        float* orow = out + (size_t)(m0 + tm + i) * OUTF + n0 + tn;
#pragma unroll
        for (int j = 0; j < 8; j++)
            orow[j] = __fadd_rn(c[i][j], bias[n0 + tn + j]);
    }
}

// ---------------------------------------------------------------------------
// JAX threefry2x32, key = (0, 42), counter = (0, c).
// x1 arrives with +ks1 already folded in (x1 = c + 42).
// Round 1's x0 += x1 with x0 == 0 is an explicit copy (saves an IMAD).
// Remaining adds forced onto the FMA pipe via mad.lo.s32 with opaque `one`.
// ---------------------------------------------------------------------------
#define KS2  (0x1BD11BDAu ^ 42u)

// x += y * one  (IMAD, fma pipe)
#define ADDF(x, y) \
    asm("mad.lo.s32 %0, %1, %2, %0;" : "+r"(x) : "r"(y), "r"(one))
// x += imm * one (IMAD with immediate, fma pipe)
#define KADD(x, imm) \
    asm("mad.lo.s32 %0, %1, %2, %0;" : "+r"(x) : "r"(one), "n"(imm))

__device__ __forceinline__ void tf2x32(uint32_t x1, uint32_t one,
                                       uint32_t& r0, uint32_t& r1)
{
#define TFR(r) { ADDF(x0, x1); x1 = __funnelshift_l(x1, x1, (r)); x1 ^= x0; }
    // Round 1: x0(=0) += x1  ==>  x0 = x1 (pure copy)
    uint32_t x0 = x1;
    x1 = __funnelshift_l(x1, x1, 13); x1 ^= x0;
    TFR(15) TFR(26) TFR(6)
    KADD(x0, 42);              // ks1
    KADD(x1, (int)(KS2 + 1u));
    TFR(17) TFR(29) TFR(16) TFR(24)
    KADD(x0, (int)KS2);
    KADD(x1, 2);               // ks0 + 2
    TFR(13) TFR(15) TFR(26) TFR(6)
    /* x0 += ks0(0) dropped */
    KADD(x1, 45);              // ks1 + 3
    TFR(17) TFR(29) TFR(16) TFR(24)
    KADD(x0, 42);              // ks1
    KADD(x1, (int)(KS2 + 4u));
    TFR(13) TFR(15) TFR(26) TFR(6)
    KADD(x0, (int)KS2);
    KADD(x1, 5);               // ks0 + 5
#undef TFR
    r0 = x0; r1 = x1;
}

// bits -> 0.3 * (sqrt(2) * erfinv(u)) — XLA-exact (unfused, EmitLog1p, Giles).
// log1p branch replaced by a branchless select (bit-identical per lane;
// __nv_logf(1+y) is safe for all y in (-1, 0]).
__device__ __forceinline__ float bits_to_noise(uint32_t bits)
{
    float f = __fsub_rn(__uint_as_float((bits >> 9) | 0x3f800000u), 1.0f);
    float u = __fadd_rn(__fmul_rn(f, 2.0f), -0.99999994f);
    u = fmaxf(u, -0.99999994f);

    float y = -__fmul_rn(u, u);
    float big   = __nv_logf(__fadd_rn(y, 1.0f));
    float small = __fmul_rn(__fadd_rn(__fmul_rn(-0.5f, y), 1.0f), y);
    float w = (fabsf(y) < 1e-4f) ? small : big;
    w = -w;

    float p;
    if (w < 5.0f) {
        w = __fsub_rn(w, 2.5f);
        p = 2.81022636e-08f;
        p = __fadd_rn(__fmul_rn(p, w),  3.43273939e-07f);
        p = __fadd_rn(__fmul_rn(p, w), -3.5233877e-06f);
        p = __fadd_rn(__fmul_rn(p, w), -4.39150654e-06f);
        p = __fadd_rn(__fmul_rn(p, w),  0.00021858087f);
        p = __fadd_rn(__fmul_rn(p, w), -0.00125372503f);
        p = __fadd_rn(__fmul_rn(p, w), -0.00417768164f);
        p = __fadd_rn(__fmul_rn(p, w),  0.246640727f);
        p = __fadd_rn(__fmul_rn(p, w),  1.50140941f);
    } else {
        w = __fsub_rn(__fsqrt_rn(w), 3.0f);
        p = -0.000200214257f;
        p = __fadd_rn(__fmul_rn(p, w),  0.000100950558f);
        p = __fadd_rn(__fmul_rn(p, w),  0.00134934322f);
        p = __fadd_rn(__fmul_rn(p, w), -0.00367342844f);
        p = __fadd_rn(__fmul_rn(p, w),  0.00573950773f);
        p = __fadd_rn(__fmul_rn(p, w), -0.0076224613f);
        p = __fadd_rn(__fmul_rn(p, w),  0.00943887047f);
        p = __fadd_rn(__fmul_rn(p, w),  1.00167406f);
        p = __fadd_rn(__fmul_rn(p, w),  2.83297682f);
    }
    float r = __fmul_rn(p, u);
    r = __fmul_rn(1.41421356f, r);
    return __fmul_rn(0.3f, r);
}

// XLA f32 rational tanh (unfused)
__device__ __forceinline__ float xla_tanhf(float x)
{
    float ax = fabsf(x);
    float xc = fminf(fmaxf(x, -7.90531110763549805f), 7.90531110763549805f);
    float x2 = __fmul_rn(xc, xc);
    float np_ = -2.76076847742355e-16f;
    np_ = __fadd_rn(__fmul_rn(np_, x2),  2.00018790482477e-13f);
    np_ = __fadd_rn(__fmul_rn(np_, x2), -8.60467152213735e-11f);
    np_ = __fadd_rn(__fmul_rn(np_, x2),  5.12229709037114e-08f);
    np_ = __fadd_rn(__fmul_rn(np_, x2),  1.48572235717979e-05f);
    np_ = __fadd_rn(__fmul_rn(np_, x2),  6.37261928875436e-04f);
    np_ = __fadd_rn(__fmul_rn(np_, x2),  4.89352455891786e-03f);
    np_ = __fmul_rn(np_, xc);
    float dp = 1.19825839466702e-06f;
    dp = __fadd_rn(__fmul_rn(dp, x2),  1.18534705686654e-04f);
    dp = __fadd_rn(__fmul_rn(dp, x2),  2.26843463243900e-03f);
    dp = __fadd_rn(__fmul_rn(dp, x2),  4.89352518554385e-03f);
    float r = __fdiv_rn(np_, dp);
    return (ax < 0.0004f) ? x : r;
}

__device__ __forceinline__ float block_reduce(float v, float* sbuf, int tid)
{
#pragma unroll
    for (int o = 16; o > 0; o >>= 1) v += __shfl_xor_sync(0xffffffffu, v, o);
    if ((tid & 31) == 0) sbuf[tid >> 5] = v;
    __syncthreads();
    if (tid < 8) {
        float t = sbuf[tid];
#pragma unroll
        for (int o = 4; o > 0; o >>= 1) t += __shfl_xor_sync(0xffu, t, o);
        if (tid == 0) sbuf[0] = t;
    }
    __syncthreads();
    float r = sbuf[0];
    __syncthreads();
    return r;
}

// ---------------------------------------------------------------------------
// Kernel 2: LN + tanh scaling + partitionable-threefry noise + 8-step
// Izhikevich, fused. One CTA per batch row; 256 threads x 8 features.
// Noise element (t,b,f): counter = (0, t*BF + b*OUTF + f), bits = r0 ^ r1.
// ---------------------------------------------------------------------------
__global__ __launch_bounds__(256)
void snn_kernel(const float* __restrict__ raw_g,
                const float* __restrict__ gamma, const float* __restrict__ beta,
                const float* __restrict__ cmag, float* __restrict__ out,
                uint32_t one)
{
    __shared__ float sbuf[8];
    const int b = blockIdx.x;
    const int tid = threadIdx.x;
    const float* rowp = raw_g + (size_t)b * OUTF;

    float vals[8];
    float s = 0.0f;
#pragma unroll
    for (int j = 0; j < 8; j++) {
        vals[j] = rowp[tid + 256 * j];
        s += vals[j];
    }
    s = block_reduce(s, sbuf, tid);
    const float mu = __fmul_rn(s, (1.0f / 2048.0f));

    float s2 = 0.0f;
#pragma unroll
    for (int j = 0; j < 8; j++) {
        float d = __fsub_rn(vals[j], mu);
        s2 += __fmul_rn(d, d);
    }
    s2 = block_reduce(s2, sbuf, tid);
    const float var = __fmul_rn(s2, (1.0f / 2048.0f));
    const float rstd = __nv_rsqrtf(__fadd_rn(var, 1e-5f));
    const float imag = fabsf(cmag[0]);

#pragma unroll 1
    for (int j = 0; j < 8; j++) {
        const int f = tid + 256 * j;
        const float d  = __fsub_rn(vals[j], mu);
        const float ln = __fadd_rn(__fmul_rn(__fmul_rn(d, rstd), gamma[f]), beta[f]);
        const float I  = __fmul_rn(xla_tanhf(ln), imag);

        // e42 = counter + ks1 folded once per element
        const uint32_t e42 = (uint32_t)b * (uint32_t)OUTF + (uint32_t)f + 42u;
        float nz[8];
#pragma unroll
        for (int t = 0; t < 8; t++) {
            uint32_t r0, r1;
            tf2x32((uint32_t)t * BF + e42, one, r0, r1);
            nz[t] = bits_to_noise(r0 ^ r1);
        }

        float v = -65.0f, uu = -13.0f, acc = 0.0f;
#pragma unroll
        for (int t = 0; t < 8; t++) {
            const float It = __fadd_rn(I, nz[t]);
            float t1 = __fmul_rn(__fmul_rn(0.04f, v), v);
            float t2 = __fmul_rn(5.0f, v);
            float sdv = __fadd_rn(t1, t2);
            sdv = __fadd_rn(sdv, 140.0f);
            sdv = __fsub_rn(sdv, uu);
            sdv = __fadd_rn(sdv, It);
            const float vn = fminf(fmaxf(__fadd_rn(v, sdv), -100.0f), 60.0f);
            float tu = __fsub_rn(__fmul_rn(0.2f, v), uu);
            tu = __fmul_rn(0.02f, tu);
            const float un = fminf(fmaxf(__fadd_rn(uu, tu), -100.0f), 100.0f);
            const bool spk = (vn >= 30.0f);
            v  = spk ? -65.0f : vn;
            uu = spk ? __fadd_rn(un, 8.0f) : un;
            acc += spk ? 1.0f : 0.0f;
        }
        out[(size_t)b * OUTF + f] = __fmul_rn(acc, 0.125f);
    }
}

// ---------------------------------------------------------------------------
extern "C" void kernel_launch(void* const* d_in, const int* in_sizes, int n_in,
                              void* d_out, int out_size)
{
    const float* x     = (const float*)d_in[0];  // [4096,1024]
    const float* W     = (const float*)d_in[1];  // [2048,1024]
    const float* b_lin = (const float*)d_in[2];  // [2048]
    const float* gamma = (const float*)d_in[3];  // [2048]
    const float* beta  = (const float*)d_in[4];  // [2048]
    const float* cmag  = (const float*)d_in[5];  // [1]
    float* out = (float*)d_out;                  // [4096,2048]

    float* raw;
    cudaGetSymbolAddress((void**)&raw, g_raw);

    // opaque 1: element count of current_mag — ptxas cannot fold this,
    // guaranteeing the mad.lo.s32 adds stay IMAD (fma pipe).
    const uint32_t one = (uint32_t)in_sizes[5];

    dim3 ggrid(OUTF / 128, BSZ / 128);
    gemm_kernel<<<ggrid, 256>>>(x, W, b_lin, raw);
    snn_kernel<<<BSZ, 256>>>(raw, gamma, beta, cmag, out, one);
}